// round 2
// baseline (speedup 1.0000x reference)
#include <cuda_runtime.h>
#include <cuda_bf16.h>
#include <cstdint>

// Hierarchical-softmax skip-gram scoring.
//   out[b] = prod_l sigmoid( sign[b,l] * dot(logistic[path_idx[b,l]], encoder[v_j[b]]) )
// with masked (padded) levels contributing 1.0. Padding is a contiguous
// suffix with path_idx == 0 (valid tree nodes are >= 2), so path_mask is
// redundant and we break on the first zero index.
//
// Layout: one warp per batch element. D = 128 floats = 32 lanes x float4,
// so every row load is one fully-coalesced 512B transaction set.

#define D 128
#define WARPS_PER_BLOCK 8
#define THREADS (WARPS_PER_BLOCK * 32)

__global__ __launch_bounds__(THREADS)
void hs_prod_kernel(const float* __restrict__ encoder,
                    const float* __restrict__ logistic,
                    const int*   __restrict__ v_j,
                    const int*   __restrict__ path_idx,
                    const int*   __restrict__ path_sign,
                    float*       __restrict__ out,
                    int B, int L) {
    const int warp = (blockIdx.x * blockDim.x + threadIdx.x) >> 5;
    const int lane = threadIdx.x & 31;
    if (warp >= B) return;

    // Gather h = encoder[v_j[b]] : lane holds h[4*lane .. 4*lane+3]
    const int j = __ldg(&v_j[warp]);
    const float4 hv =
        reinterpret_cast<const float4*>(encoder + (size_t)j * D)[lane];

    // Preload this element's whole path into lane registers (L <= 32).
    int my_idx = 0, my_sgn = 0;
    if (lane < L) {
        my_idx = __ldg(&path_idx[(size_t)warp * L + lane]);
        my_sgn = __ldg(&path_sign[(size_t)warp * L + lane]);
    }

    float prod = 1.0f;
    #pragma unroll 4
    for (int l = 0; l < L; ++l) {
        const int idx = __shfl_sync(0xffffffffu, my_idx, l);
        if (idx == 0) break;                         // contiguous padding suffix
        const int sgn = __shfl_sync(0xffffffffu, my_sgn, l);

        const float4 wv =
            reinterpret_cast<const float4*>(logistic + (size_t)idx * D)[lane];

        float s = wv.x * hv.x + wv.y * hv.y + wv.z * hv.z + wv.w * hv.w;
        #pragma unroll
        for (int o = 16; o > 0; o >>= 1)
            s += __shfl_xor_sync(0xffffffffu, s, o);

        const float logit = s * (float)sgn;
        prod *= 1.0f / (1.0f + expf(-logit));        // matches jax.nn.sigmoid in fp32
    }

    if (lane == 0) out[warp] = prod;
}

extern "C" void kernel_launch(void* const* d_in, const int* in_sizes, int n_in,
                              void* d_out, int out_size) {
    // metadata order: encoder, logistic, v_j, path_idx, path_sign, path_mask
    const float* encoder  = (const float*)d_in[0];
    const float* logistic = (const float*)d_in[1];
    const int*   v_j      = (const int*)  d_in[2];
    const int*   path_idx = (const int*)  d_in[3];
    const int*   path_sign= (const int*)  d_in[4];
    float*       out      = (float*)      d_out;

    const int B = in_sizes[2];
    const int L = in_sizes[3] / B;

    const int blocks = (B + WARPS_PER_BLOCK - 1) / WARPS_PER_BLOCK;
    hs_prod_kernel<<<blocks, THREADS>>>(encoder, logistic, v_j, path_idx,
                                        path_sign, out, B, L);
}

// round 3
// speedup vs baseline: 1.1775x; 1.1775x over previous
#include <cuda_runtime.h>
#include <cuda_bf16.h>
#include <cstdint>

// Hierarchical-softmax skip-gram scoring.
//   out[b] = prod_l sigmoid( sign[b,l] * dot(logistic[path_idx[b,l]], encoder[v_j[b]]) )
// Padded levels have path_sign == 0 (and path_idx == 0), so sign==0 is the mask.
//
// One warp per batch element; D = 128 = 32 lanes x float4.
// Phase 1: all L row loads issued with full MLP (no break, fully unrolled).
// Phase 2: butterfly-transpose multi-value reduce — 31 shuffles total deliver
//          level-l's full dot product to lane l.
// Phase 3: per-lane sigmoid (parallel across levels) + 5-shuffle product.

#define D 128
#define WARPS_PER_BLOCK 8
#define THREADS (WARPS_PER_BLOCK * 32)
#define FULL 0xffffffffu

template <int LMAX>
__global__ __launch_bounds__(THREADS)
void hs_prod_kernel(const float* __restrict__ encoder,
                    const float* __restrict__ logistic,
                    const int*   __restrict__ v_j,
                    const int*   __restrict__ path_idx,
                    const int*   __restrict__ path_sign,
                    float*       __restrict__ out,
                    int B, int L) {
    const int warp = (blockIdx.x * blockDim.x + threadIdx.x) >> 5;
    const int lane = threadIdx.x & 31;
    if (warp >= B) return;

    // h = encoder[v_j[b]] : lane holds h[4*lane .. 4*lane+3]
    const int j = __ldg(&v_j[warp]);
    const float4 hv =
        reinterpret_cast<const float4*>(encoder + (size_t)j * D)[lane];

    // lane l owns (idx, sign) of level l  (L <= 32)
    int my_idx = 0, my_sgn = 0;
    if (lane < L) {
        my_idx = __ldg(&path_idx[(size_t)warp * L + lane]);
        my_sgn = __ldg(&path_sign[(size_t)warp * L + lane]);
    }

    // ---- Phase 1: per-level partial dots, all loads in flight ----
    float a[LMAX];
    #pragma unroll
    for (int l = 0; l < LMAX; ++l) {
        a[l] = 0.0f;
        if (l < L) {
            const int idx = __shfl_sync(FULL, my_idx, l);
            const float4 wv =
                reinterpret_cast<const float4*>(logistic + (size_t)idx * D)[lane];
            a[l] = wv.x * hv.x + wv.y * hv.y + wv.z * hv.z + wv.w * hv.w;
        }
    }

    // ---- Phase 2: transpose-reduce. After this, lane g holds the complete
    // dot product of level g in a[0]. 16+8+4+2+1 = 31 shuffles total.
    #pragma unroll
    for (int h = 16; h >= 1; h >>= 1) {
        #pragma unroll
        for (int l = 0; l < h; ++l) {
            const float lo = a[l];
            const float hi = (l + h < LMAX) ? a[l + h] : 0.0f;
            const bool  up = (lane & h) != 0;
            const float send = up ? lo : hi;
            const float keep = up ? hi : lo;
            a[l] = keep + __shfl_xor_sync(FULL, send, h);
        }
    }

    // ---- Phase 3: per-lane sigmoid (lane == level), then product reduce ----
    float prob = 1.0f;
    if (my_sgn != 0) {
        const float x = a[0] * (float)my_sgn;
        prob = __fdividef(1.0f, 1.0f + __expf(-x));
    }
    #pragma unroll
    for (int o = 16; o > 0; o >>= 1)
        prob *= __shfl_xor_sync(FULL, prob, o);

    if (lane == 0) out[warp] = prob;
}

// Generic fallback for L > 32 (cannot happen for this problem, but safe).
__global__ __launch_bounds__(THREADS)
void hs_prod_generic(const float* __restrict__ encoder,
                     const float* __restrict__ logistic,
                     const int*   __restrict__ v_j,
                     const int*   __restrict__ path_idx,
                     const int*   __restrict__ path_sign,
                     float*       __restrict__ out,
                     int B, int L) {
    const int warp = (blockIdx.x * blockDim.x + threadIdx.x) >> 5;
    const int lane = threadIdx.x & 31;
    if (warp >= B) return;
    const int j = __ldg(&v_j[warp]);
    const float4 hv =
        reinterpret_cast<const float4*>(encoder + (size_t)j * D)[lane];
    float prod = 1.0f;
    for (int l = 0; l < L; ++l) {
        const int idx = __ldg(&path_idx[(size_t)warp * L + l]);
        const int sgn = __ldg(&path_sign[(size_t)warp * L + l]);
        if (sgn == 0) continue;
        const float4 wv =
            reinterpret_cast<const float4*>(logistic + (size_t)idx * D)[lane];
        float s = wv.x * hv.x + wv.y * hv.y + wv.z * hv.z + wv.w * hv.w;
        #pragma unroll
        for (int o = 16; o > 0; o >>= 1)
            s += __shfl_xor_sync(FULL, s, o);
        prod *= __fdividef(1.0f, 1.0f + __expf(-s * (float)sgn));
    }
    if (lane == 0) out[warp] = prod;
}

extern "C" void kernel_launch(void* const* d_in, const int* in_sizes, int n_in,
                              void* d_out, int out_size) {
    // metadata order: encoder, logistic, v_j, path_idx, path_sign, path_mask
    const float* encoder  = (const float*)d_in[0];
    const float* logistic = (const float*)d_in[1];
    const int*   v_j      = (const int*)  d_in[2];
    const int*   path_idx = (const int*)  d_in[3];
    const int*   path_sign= (const int*)  d_in[4];
    float*       out      = (float*)      d_out;

    const int B = in_sizes[2];
    const int L = in_sizes[3] / B;

    const int blocks = (B + WARPS_PER_BLOCK - 1) / WARPS_PER_BLOCK;
    if (L <= 20) {
        hs_prod_kernel<20><<<blocks, THREADS>>>(encoder, logistic, v_j,
                                                path_idx, path_sign, out, B, L);
    } else if (L <= 32) {
        hs_prod_kernel<32><<<blocks, THREADS>>>(encoder, logistic, v_j,
                                                path_idx, path_sign, out, B, L);
    } else {
        hs_prod_generic<<<blocks, THREADS>>>(encoder, logistic, v_j,
                                             path_idx, path_sign, out, B, L);
    }
}